// round 1
// baseline (speedup 1.0000x reference)
#include <cuda_runtime.h>
#include <math_constants.h>

// Problem constants
#define P_ELEMS (96*96*96)          // 884736 points per sample
#define NSAMP   4
#define NB      32
#define NBINS2  (NB*NB)

// exponent constant: -(d^2)/(2*sigma^2) with d = delta_bins/31, sigma = 1/64
// => -(delta^2) * (2048/961) = -(delta^2) * 2.1311134...
#define EXP_C   2.13111342352757f

// Scratch in device globals (no allocations allowed)
__device__ unsigned g_mn[2*NSAMP];          // [0..3]=tar, [4..7]=src (float bits, vals >= 0)
__device__ unsigned g_mx[2*NSAMP];
__device__ float    g_hist[NSAMP*NBINS2];   // per-sample 32x32 joint hist

// ---------------------------------------------------------------------------
__global__ void k_init() {
    int tid = blockIdx.x * blockDim.x + threadIdx.x;
    if (tid < NSAMP*NBINS2) g_hist[tid] = 0.0f;
    if (tid < 2*NSAMP) { g_mn[tid] = 0x7F800000u; g_mx[tid] = 0u; }  // +inf / 0.0
}

// ---------------------------------------------------------------------------
// Per-sample min/max of tar and src (values are >= 0, so uint bit compare works)
__global__ void k_minmax(const float* __restrict__ tar, const float* __restrict__ src) {
    int b = blockIdx.y;
    const float4* t4 = (const float4*)(tar + (size_t)b * P_ELEMS);
    const float4* s4 = (const float4*)(src + (size_t)b * P_ELEMS);
    const int n4 = P_ELEMS / 4;

    float mnT =  1e30f, mxT = -1e30f, mnS = 1e30f, mxS = -1e30f;
    for (int i = blockIdx.x * blockDim.x + threadIdx.x; i < n4; i += gridDim.x * blockDim.x) {
        float4 v = t4[i];
        mnT = fminf(mnT, fminf(fminf(v.x, v.y), fminf(v.z, v.w)));
        mxT = fmaxf(mxT, fmaxf(fmaxf(v.x, v.y), fmaxf(v.z, v.w)));
        float4 u = s4[i];
        mnS = fminf(mnS, fminf(fminf(u.x, u.y), fminf(u.z, u.w)));
        mxS = fmaxf(mxS, fmaxf(fmaxf(u.x, u.y), fmaxf(u.z, u.w)));
    }
    #pragma unroll
    for (int o = 16; o > 0; o >>= 1) {
        mnT = fminf(mnT, __shfl_xor_sync(0xffffffffu, mnT, o));
        mxT = fmaxf(mxT, __shfl_xor_sync(0xffffffffu, mxT, o));
        mnS = fminf(mnS, __shfl_xor_sync(0xffffffffu, mnS, o));
        mxS = fmaxf(mxS, __shfl_xor_sync(0xffffffffu, mxS, o));
    }
    __shared__ float sm[4][8];
    int w = threadIdx.x >> 5;
    if ((threadIdx.x & 31) == 0) {
        sm[0][w] = mnT; sm[1][w] = mxT; sm[2][w] = mnS; sm[3][w] = mxS;
    }
    __syncthreads();
    if (threadIdx.x == 0) {
        float a = sm[0][0], c = sm[1][0], e = sm[2][0], f = sm[3][0];
        #pragma unroll
        for (int i = 1; i < 8; i++) {
            a = fminf(a, sm[0][i]); c = fmaxf(c, sm[1][i]);
            e = fminf(e, sm[2][i]); f = fmaxf(f, sm[3][i]);
        }
        atomicMin(&g_mn[b],   __float_as_uint(a));
        atomicMax(&g_mx[b],   __float_as_uint(c));
        atomicMin(&g_mn[4+b], __float_as_uint(e));
        atomicMax(&g_mx[4+b], __float_as_uint(f));
    }
}

// ---------------------------------------------------------------------------
// Joint histogram with truncated (9-bin) Gaussian windows.
// Per-warp private smem histograms (8 x 1024 floats = 32 KB) to cut contention.
__global__ void __launch_bounds__(256) k_hist(const float* __restrict__ tar,
                                              const float* __restrict__ src) {
    __shared__ float sh[8 * NBINS2];
    int b = blockIdx.y;
    for (int i = threadIdx.x; i < 8 * NBINS2; i += blockDim.x) sh[i] = 0.0f;
    __syncthreads();

    float mnT = __uint_as_float(g_mn[b]),   mxT = __uint_as_float(g_mx[b]);
    float mnS = __uint_as_float(g_mn[4+b]), mxS = __uint_as_float(g_mx[4+b]);
    // fi = (x - mn)/(mx - mn + 1e-12) * 31  (bin-index space)
    float scT = 31.0f / (mxT - mnT + 1e-12f);
    float scS = 31.0f / (mxS - mnS + 1e-12f);

    float* wh = sh + ((threadIdx.x >> 5) * NBINS2);
    const float* tp = tar + (size_t)b * P_ELEMS;
    const float* sp = src + (size_t)b * P_ELEMS;

    for (int p = blockIdx.x * blockDim.x + threadIdx.x; p < P_ELEMS;
         p += gridDim.x * blockDim.x) {
        float ft = (tp[p] - mnT) * scT;       // in [0, 31]
        float fs = (sp[p] - mnS) * scS;
        int it0 = min(max(__float2int_rn(ft) - 4, 0), NB - 9);
        int js0 = min(max(__float2int_rn(fs) - 4, 0), NB - 9);

        float wt[9], ws[9];
        #pragma unroll
        for (int k = 0; k < 9; k++) {
            float d = ft - (float)(it0 + k);
            wt[k] = __expf(-d * d * EXP_C);
        }
        #pragma unroll
        for (int k = 0; k < 9; k++) {
            float d = fs - (float)(js0 + k);
            ws[k] = __expf(-d * d * EXP_C);
        }

        float* base = wh + it0 * NB + js0;
        #pragma unroll
        for (int k = 0; k < 9; k++) {
            float w = wt[k];
            float* row = base + k * NB;
            #pragma unroll
            for (int l = 0; l < 9; l++) {
                atomicAdd(row + l, w * ws[l]);
            }
        }
    }

    __syncthreads();
    for (int i = threadIdx.x; i < NBINS2; i += blockDim.x) {
        float s = 0.0f;
        #pragma unroll
        for (int w = 0; w < 8; w++) s += sh[w * NBINS2 + i];
        atomicAdd(&g_hist[b * NBINS2 + i], s);
    }
}

// ---------------------------------------------------------------------------
// Finalize: entropies + loss. One CTA of 1024 threads (tid = i*32 + j).
__device__ __forceinline__ float blockSum1024(float v) {
    __shared__ float red[33];
    int lane = threadIdx.x & 31, w = threadIdx.x >> 5;
    #pragma unroll
    for (int o = 16; o > 0; o >>= 1) v += __shfl_xor_sync(0xffffffffu, v, o);
    __syncthreads();                 // protect red[] reuse across calls
    if (lane == 0) red[w] = v;
    __syncthreads();
    if (w == 0) {
        float x = red[lane];
        #pragma unroll
        for (int o = 16; o > 0; o >>= 1) x += __shfl_xor_sync(0xffffffffu, x, o);
        if (lane == 0) red[32] = x;
    }
    __syncthreads();
    return red[32];
}

__global__ void __launch_bounds__(1024) k_final(float* __restrict__ out) {
    __shared__ float pbuf[NBINS2];
    const int tid = threadIdx.x;
    const float EPS = 1e-10f;
    float acc = 0.0f;

    for (int b = 0; b < NSAMP; b++) {
        float h = g_hist[b * NBINS2 + tid];
        float norm = blockSum1024(h);
        float p = h / norm;
        pbuf[tid] = p;

        float entJ = -blockSum1024(p * logf(p + EPS));

        // row marginal: warp w == tar bin i, lanes are src bins j
        float pr = p;
        #pragma unroll
        for (int o = 16; o > 0; o >>= 1) pr += __shfl_xor_sync(0xffffffffu, pr, o);
        float vt = ((tid & 31) == 0) ? pr * logf(pr + EPS) : 0.0f;
        float entT = -blockSum1024(vt);

        // column marginal: first 32 threads each sum a column of pbuf
        float vs = 0.0f;
        if (tid < NB) {
            float cs = 0.0f;
            #pragma unroll
            for (int i = 0; i < NB; i++) cs += pbuf[i * NB + tid];
            vs = cs * logf(cs + EPS);
        }
        float entS = -blockSum1024(vs);

        acc += (entT + entS) / entJ;
    }
    if (tid == 0) out[0] = -acc * (1.0f / (float)NSAMP);
}

// ---------------------------------------------------------------------------
extern "C" void kernel_launch(void* const* d_in, const int* in_sizes, int n_in,
                              void* d_out, int out_size) {
    const float* tar = (const float*)d_in[0];
    const float* src = (const float*)d_in[1];
    float* out = (float*)d_out;

    k_init<<<16, 256>>>();
    k_minmax<<<dim3(64, NSAMP), 256>>>(tar, src);
    k_hist<<<dim3(148, NSAMP), 256>>>(tar, src);
    k_final<<<1, 1024>>>(out);
}

// round 2
// speedup vs baseline: 3.7102x; 3.7102x over previous
#include <cuda_runtime.h>

// ---------------------------------------------------------------------------
// Problem constants
#define P_ELEMS (96*96*96)          // 884736 points per sample
#define NSAMP   4
#define NB      32
#define NBINS2  (NB*NB)
#define MM_CTAS 16                  // minmax partial CTAs per sample
#define HQ      (P_ELEMS/4)         // per-launch point quarter (221184)

// exp(-(d^2)/(2 sigma^2)) with d in bin units: coeff = 2048/961 = 2.1311134
// folded into exp2: 2.1311134 * log2(e) = 3.0745468
#define EXP2_C  3.0745468f

// ---------------------------------------------------------------------------
// Device scratch (no allocations allowed)
__device__ float g_pmnT[NSAMP*MM_CTAS];
__device__ float g_pmxT[NSAMP*MM_CTAS];
__device__ float g_pmnS[NSAMP*MM_CTAS];
__device__ float g_pmxS[NSAMP*MM_CTAS];
__device__ float g_hist[NSAMP*NBINS2];
__device__ float g_norm[NSAMP];

// ---------------------------------------------------------------------------
// Pass 1: per-CTA min/max partials (plain stores, no atomics/init needed).
// Also zeroes g_hist (sample-0 CTAs own disjoint ranges).
__global__ void __launch_bounds__(256) k_pre(const float* __restrict__ tar,
                                             const float* __restrict__ src) {
    int b = blockIdx.y;
    if (b == 0) {
        int idx = blockIdx.x * 256 + threadIdx.x;       // 16*256 = 4096 = NSAMP*NBINS2
        g_hist[idx] = 0.0f;
    }

    const float4* t4 = (const float4*)(tar + (size_t)b * P_ELEMS);
    const float4* s4 = (const float4*)(src + (size_t)b * P_ELEMS);
    const int n4 = P_ELEMS / 4;

    float mnT = 1e30f, mxT = -1e30f, mnS = 1e30f, mxS = -1e30f;
    for (int i = blockIdx.x * 256 + threadIdx.x; i < n4; i += MM_CTAS * 256) {
        float4 v = t4[i];
        mnT = fminf(mnT, fminf(fminf(v.x, v.y), fminf(v.z, v.w)));
        mxT = fmaxf(mxT, fmaxf(fmaxf(v.x, v.y), fmaxf(v.z, v.w)));
        float4 u = s4[i];
        mnS = fminf(mnS, fminf(fminf(u.x, u.y), fminf(u.z, u.w)));
        mxS = fmaxf(mxS, fmaxf(fmaxf(u.x, u.y), fmaxf(u.z, u.w)));
    }
    #pragma unroll
    for (int o = 16; o > 0; o >>= 1) {
        mnT = fminf(mnT, __shfl_xor_sync(0xffffffffu, mnT, o));
        mxT = fmaxf(mxT, __shfl_xor_sync(0xffffffffu, mxT, o));
        mnS = fminf(mnS, __shfl_xor_sync(0xffffffffu, mnS, o));
        mxS = fmaxf(mxS, __shfl_xor_sync(0xffffffffu, mxS, o));
    }
    __shared__ float sm[4][8];
    int w = threadIdx.x >> 5;
    if ((threadIdx.x & 31) == 0) {
        sm[0][w] = mnT; sm[1][w] = mxT; sm[2][w] = mnS; sm[3][w] = mxS;
    }
    __syncthreads();
    if (threadIdx.x == 0) {
        float a = sm[0][0], c = sm[1][0], e = sm[2][0], f = sm[3][0];
        #pragma unroll
        for (int i = 1; i < 8; i++) {
            a = fminf(a, sm[0][i]); c = fmaxf(c, sm[1][i]);
            e = fminf(e, sm[2][i]); f = fmaxf(f, sm[3][i]);
        }
        int slot = b * MM_CTAS + blockIdx.x;
        g_pmnT[slot] = a; g_pmxT[slot] = c;
        g_pmnS[slot] = e; g_pmxS[slot] = f;
    }
}

// ---------------------------------------------------------------------------
// Pass 2: joint histogram, 7x7 truncated Gaussian window.
// Lane-interleaved private histograms: copy per lane, addr = bin*32 + lane
// => bank == lane => conflict-free shared atomics within every warp inst.
// 1024 bins * 32 lanes * 4B = 128 KB dynamic smem, 1 CTA/SM.
__global__ void __launch_bounds__(512) k_hist(const float* __restrict__ tar,
                                              const float* __restrict__ src,
                                              int pbase, int pcount) {
    extern __shared__ float sh[];           // [NBINS2][32]
    const int b = blockIdx.y;

    // zero the 128 KB
    float4* z4 = (float4*)sh;
    #pragma unroll
    for (int i = threadIdx.x; i < NBINS2 * 32 / 4; i += 512)
        z4[i] = make_float4(0.f, 0.f, 0.f, 0.f);

    // reduce the 16 minmax partials (threads 0..3, one stat each)
    __shared__ float lim[4];
    if (threadIdx.x < 4) {
        const float* arr = (threadIdx.x == 0) ? g_pmnT :
                           (threadIdx.x == 1) ? g_pmxT :
                           (threadIdx.x == 2) ? g_pmnS : g_pmxS;
        bool ismin = (threadIdx.x & 1) == 0;
        float r = arr[b * MM_CTAS];
        #pragma unroll
        for (int i = 1; i < MM_CTAS; i++) {
            float v = arr[b * MM_CTAS + i];
            r = ismin ? fminf(r, v) : fmaxf(r, v);
        }
        lim[threadIdx.x] = r;
    }
    __syncthreads();

    const float mnT = lim[0], mxT = lim[1], mnS = lim[2], mxS = lim[3];
    const float scT = 31.0f / (mxT - mnT + 1e-12f);
    const float scS = 31.0f / (mxS - mnS + 1e-12f);

    const float* tp = tar + (size_t)b * P_ELEMS;
    const float* sp = src + (size_t)b * P_ELEMS;
    float* hb = sh + (threadIdx.x & 31);    // this lane's copy base

    const int pend = pbase + pcount;
    for (int p = pbase + blockIdx.x * 512 + threadIdx.x; p < pend;
         p += gridDim.x * 512) {
        float ft = (tp[p] - mnT) * scT;     // in [0, 31]
        float fs = (sp[p] - mnS) * scS;
        int it0 = min(max(__float2int_rn(ft) - 3, 0), NB - 7);
        int js0 = min(max(__float2int_rn(fs) - 3, 0), NB - 7);

        float wt[7], ws[7];
        #pragma unroll
        for (int k = 0; k < 7; k++) {
            float d = ft - (float)(it0 + k);
            wt[k] = exp2f(-EXP2_C * d * d);
        }
        #pragma unroll
        for (int k = 0; k < 7; k++) {
            float d = fs - (float)(js0 + k);
            ws[k] = exp2f(-EXP2_C * d * d);
        }

        float* base = hb + ((it0 * NB + js0) << 5);
        #pragma unroll
        for (int k = 0; k < 7; k++) {
            float w = wt[k];
            #pragma unroll
            for (int l = 0; l < 7; l++) {
                atomicAdd(base + (((k * NB) + l) << 5), w * ws[l]);
            }
        }
    }

    __syncthreads();
    // merge 32 lane copies per bin, rotated reads (bank = (lane+i)&31: conflict-free)
    const int lane = threadIdx.x & 31;
    for (int bin = threadIdx.x; bin < NBINS2; bin += 512) {
        const float* c = sh + (bin << 5);
        float s = 0.0f;
        #pragma unroll
        for (int i = 0; i < 32; i++) s += c[(lane + i) & 31];
        atomicAdd(&g_hist[b * NBINS2 + bin], s);
    }
}

// ---------------------------------------------------------------------------
// Pass 3: per-sample histogram norm (4 CTAs x 1024 threads)
__global__ void __launch_bounds__(1024) k_norm() {
    __shared__ float red[32];
    int b = blockIdx.x;
    float v = g_hist[b * NBINS2 + threadIdx.x];
    int lane = threadIdx.x & 31, w = threadIdx.x >> 5;
    #pragma unroll
    for (int o = 16; o > 0; o >>= 1) v += __shfl_xor_sync(0xffffffffu, v, o);
    if (lane == 0) red[w] = v;
    __syncthreads();
    if (w == 0) {
        float x = red[lane];
        #pragma unroll
        for (int o = 16; o > 0; o >>= 1) x += __shfl_xor_sync(0xffffffffu, x, o);
        if (lane == 0) g_norm[b] = x;
    }
}

// ---------------------------------------------------------------------------
// Pass 4: entropies + loss. 1 CTA, warp w handles sample w, shuffle-only.
__global__ void __launch_bounds__(128) k_final(float* __restrict__ out) {
    __shared__ float part[4];
    const int w = threadIdx.x >> 5, lane = threadIdx.x & 31;
    const float EPS = 1e-10f;

    float inv = 1.0f / g_norm[w];
    float v[32];
    #pragma unroll
    for (int i = 0; i < 32; i++)
        v[i] = g_hist[w * NBINS2 + i * NB + lane] * inv;   // column 'lane' of p

    float cs = 0.0f, ej = 0.0f;
    #pragma unroll
    for (int i = 0; i < 32; i++) {
        cs += v[i];
        ej += v[i] * logf(v[i] + EPS);        // ej = sum p log p = -entJoint (partial)
    }
    #pragma unroll
    for (int o = 16; o > 0; o >>= 1) ej += __shfl_xor_sync(0xffffffffu, ej, o);

    float es = cs * logf(cs + EPS);           // col marginal term
    #pragma unroll
    for (int o = 16; o > 0; o >>= 1) es += __shfl_xor_sync(0xffffffffu, es, o);

    // full-vector butterfly: every lane ends with all 32 row sums
    #pragma unroll
    for (int o = 16; o > 0; o >>= 1) {
        #pragma unroll
        for (int i = 0; i < 32; i++) v[i] += __shfl_xor_sync(0xffffffffu, v[i], o);
    }
    float et = 0.0f;
    #pragma unroll
    for (int i = 0; i < 32; i++) et += v[i] * logf(v[i] + EPS);

    // (entT + entS)/entJ == (et + es)/ej   (both numerator and denominator negated)
    float val = (et + es) / ej;
    if (lane == 0) part[w] = val;
    __syncthreads();
    if (threadIdx.x == 0)
        out[0] = -(part[0] + part[1] + part[2] + part[3]) * 0.25f;
}

// ---------------------------------------------------------------------------
extern "C" void kernel_launch(void* const* d_in, const int* in_sizes, int n_in,
                              void* d_out, int out_size) {
    const float* tar = (const float*)d_in[0];
    const float* src = (const float*)d_in[1];
    float* out = (float*)d_out;

    static bool attr_set = false;
    if (!attr_set) {
        cudaFuncSetAttribute(k_hist, cudaFuncAttributeMaxDynamicSharedMemorySize,
                             NBINS2 * 32 * sizeof(float));
        attr_set = true;
    }

    k_pre<<<dim3(MM_CTAS, NSAMP), 256>>>(tar, src);
    for (int q = 0; q < 4; q++)
        k_hist<<<dim3(37, NSAMP), 512, NBINS2 * 32 * sizeof(float)>>>(tar, src, q * HQ, HQ);
    k_norm<<<NSAMP, 1024>>>();
    k_final<<<1, 128>>>(out);
}

// round 3
// speedup vs baseline: 9.7854x; 2.6375x over previous
#include <cuda_runtime.h>

// ---------------------------------------------------------------------------
// Problem constants
#define P_ELEMS (96*96*96)          // 884736 points per sample
#define NSAMP   4
#define NB      32
#define NBINS2  (NB*NB)
#define MM_CTAS 37                  // minmax partial CTAs per sample (37*4=148)

// exp(-(d^2)/(2 sigma^2)) with d in bin units: C = 2048/961 = 2.1311134235
// exp2 form: C*log2(e) = 3.0745468
#define EXP2_C   3.0745468f
#define EXP2_2C  6.1490936f
// g_t = exp(-C*t^2):
#define G1 0.1187046f               // exp(-C)
#define G2 1.98550e-4f              // exp(-4C)

// ---------------------------------------------------------------------------
// Device scratch (no allocations allowed)
__device__ float g_pmnT[NSAMP*MM_CTAS];
__device__ float g_pmxT[NSAMP*MM_CTAS];
__device__ float g_pmnS[NSAMP*MM_CTAS];
__device__ float g_pmxS[NSAMP*MM_CTAS];
__device__ float g_hist[NSAMP*NBINS2];
__device__ float g_norm[NSAMP];

// ---------------------------------------------------------------------------
// Pass 1: per-CTA min/max partials (plain stores). Also zeroes g_hist.
__global__ void __launch_bounds__(256) k_pre(const float* __restrict__ tar,
                                             const float* __restrict__ src) {
    int b = blockIdx.y;
    if (b == 0) {
        int idx = blockIdx.x * 256 + threadIdx.x;
        if (idx < NSAMP * NBINS2) g_hist[idx] = 0.0f;
    }

    const float4* t4 = (const float4*)(tar + (size_t)b * P_ELEMS);
    const float4* s4 = (const float4*)(src + (size_t)b * P_ELEMS);
    const int n4 = P_ELEMS / 4;

    float mnT = 1e30f, mxT = -1e30f, mnS = 1e30f, mxS = -1e30f;
    for (int i = blockIdx.x * 256 + threadIdx.x; i < n4; i += MM_CTAS * 256) {
        float4 v = t4[i];
        mnT = fminf(mnT, fminf(fminf(v.x, v.y), fminf(v.z, v.w)));
        mxT = fmaxf(mxT, fmaxf(fmaxf(v.x, v.y), fmaxf(v.z, v.w)));
        float4 u = s4[i];
        mnS = fminf(mnS, fminf(fminf(u.x, u.y), fminf(u.z, u.w)));
        mxS = fmaxf(mxS, fmaxf(fmaxf(u.x, u.y), fmaxf(u.z, u.w)));
    }
    #pragma unroll
    for (int o = 16; o > 0; o >>= 1) {
        mnT = fminf(mnT, __shfl_xor_sync(0xffffffffu, mnT, o));
        mxT = fmaxf(mxT, __shfl_xor_sync(0xffffffffu, mxT, o));
        mnS = fminf(mnS, __shfl_xor_sync(0xffffffffu, mnS, o));
        mxS = fmaxf(mxS, __shfl_xor_sync(0xffffffffu, mxS, o));
    }
    __shared__ float sm[4][8];
    int w = threadIdx.x >> 5;
    if ((threadIdx.x & 31) == 0) {
        sm[0][w] = mnT; sm[1][w] = mxT; sm[2][w] = mnS; sm[3][w] = mxS;
    }
    __syncthreads();
    if (threadIdx.x == 0) {
        float a = sm[0][0], c = sm[1][0], e = sm[2][0], f = sm[3][0];
        #pragma unroll
        for (int i = 1; i < 8; i++) {
            a = fminf(a, sm[0][i]); c = fmaxf(c, sm[1][i]);
            e = fminf(e, sm[2][i]); f = fmaxf(f, sm[3][i]);
        }
        int slot = b * MM_CTAS + blockIdx.x;
        g_pmnT[slot] = a; g_pmxT[slot] = c;
        g_pmnS[slot] = e; g_pmxS[slot] = f;
    }
}

// ---------------------------------------------------------------------------
// 5-wide Gaussian window via ratio chain: 3 EX2 per axis instead of 5.
// w[t] = exp(-C*(m-(t-2))^2) for t=0..4, m = f - (i0+2) in [-2.5, 2.5].
__device__ __forceinline__ void gauss5(float f, int& i0, float w[5]) {
    int c = __float2int_rn(f);
    i0 = min(max(c - 2, 0), NB - 5);
    float m = f - (float)(i0 + 2);
    float e0 = exp2f(-EXP2_C * m * m);
    float rp = exp2f( EXP2_2C * m);
    float rm = exp2f(-EXP2_2C * m);
    w[2] = e0;
    float a = e0 * G1;
    w[3] = a * rp;
    w[1] = a * rm;
    float b = e0 * G2;
    w[4] = b * (rp * rp);
    w[0] = b * (rm * rm);
}

// ---------------------------------------------------------------------------
// Pass 2: joint histogram, 5x5 truncated Gaussian window.
// Lane-interleaved private histograms (bank == lane, conflict-free ATOMS).
// 128 KB dynamic smem, 1024 threads, 1 CTA/SM, grid = (37, 4) = 1 full wave.
__global__ void __launch_bounds__(1024, 1) k_hist(const float* __restrict__ tar,
                                                  const float* __restrict__ src) {
    extern __shared__ float sh[];           // [NBINS2][32]
    const int b = blockIdx.y;

    float4* z4 = (float4*)sh;
    #pragma unroll
    for (int i = threadIdx.x; i < NBINS2 * 32 / 4; i += 1024)
        z4[i] = make_float4(0.f, 0.f, 0.f, 0.f);

    __shared__ float lim[4];
    if (threadIdx.x < 4) {
        const float* arr = (threadIdx.x == 0) ? g_pmnT :
                           (threadIdx.x == 1) ? g_pmxT :
                           (threadIdx.x == 2) ? g_pmnS : g_pmxS;
        bool ismin = (threadIdx.x & 1) == 0;
        float r = arr[b * MM_CTAS];
        #pragma unroll
        for (int i = 1; i < MM_CTAS; i++) {
            float v = arr[b * MM_CTAS + i];
            r = ismin ? fminf(r, v) : fmaxf(r, v);
        }
        lim[threadIdx.x] = r;
    }
    __syncthreads();

    const float mnT = lim[0], mxT = lim[1], mnS = lim[2], mxS = lim[3];
    const float scT = 31.0f / (mxT - mnT + 1e-12f);
    const float scS = 31.0f / (mxS - mnS + 1e-12f);

    const float* tp = tar + (size_t)b * P_ELEMS;
    const float* sp = src + (size_t)b * P_ELEMS;
    float* hb = sh + (threadIdx.x & 31);    // this lane's copy base

    for (int p = blockIdx.x * 1024 + threadIdx.x; p < P_ELEMS;
         p += gridDim.x * 1024) {
        float ft = (tp[p] - mnT) * scT;     // in [0, 31]
        float fs = (sp[p] - mnS) * scS;

        int it0, js0;
        float wt[5], ws[5];
        gauss5(ft, it0, wt);
        gauss5(fs, js0, ws);

        float* base = hb + ((it0 * NB + js0) << 5);
        #pragma unroll
        for (int k = 0; k < 5; k++) {
            float w = wt[k];
            #pragma unroll
            for (int l = 0; l < 5; l++) {
                atomicAdd(base + (((k * NB) + l) << 5), w * ws[l]);
            }
        }
    }

    __syncthreads();
    // merge 32 lane copies per bin, rotated reads (conflict-free)
    const int lane = threadIdx.x & 31;
    for (int bin = threadIdx.x; bin < NBINS2; bin += 1024) {
        const float* c = sh + (bin << 5);
        float s = 0.0f;
        #pragma unroll
        for (int i = 0; i < 32; i++) s += c[(lane + i) & 31];
        atomicAdd(&g_hist[b * NBINS2 + bin], s);
    }
}

// ---------------------------------------------------------------------------
// Pass 3: per-sample histogram norm
__global__ void __launch_bounds__(1024) k_norm() {
    __shared__ float red[32];
    int b = blockIdx.x;
    float v = g_hist[b * NBINS2 + threadIdx.x];
    int lane = threadIdx.x & 31, w = threadIdx.x >> 5;
    #pragma unroll
    for (int o = 16; o > 0; o >>= 1) v += __shfl_xor_sync(0xffffffffu, v, o);
    if (lane == 0) red[w] = v;
    __syncthreads();
    if (w == 0) {
        float x = red[lane];
        #pragma unroll
        for (int o = 16; o > 0; o >>= 1) x += __shfl_xor_sync(0xffffffffu, x, o);
        if (lane == 0) g_norm[b] = x;
    }
}

// ---------------------------------------------------------------------------
// Pass 4: entropies + loss. 1 CTA, warp w handles sample w, shuffle-only.
__global__ void __launch_bounds__(128) k_final(float* __restrict__ out) {
    __shared__ float part[4];
    const int w = threadIdx.x >> 5, lane = threadIdx.x & 31;
    const float EPS = 1e-10f;

    float inv = 1.0f / g_norm[w];
    float v[32];
    #pragma unroll
    for (int i = 0; i < 32; i++)
        v[i] = g_hist[w * NBINS2 + i * NB + lane] * inv;   // column 'lane' of p

    float cs = 0.0f, ej = 0.0f;
    #pragma unroll
    for (int i = 0; i < 32; i++) {
        cs += v[i];
        ej += v[i] * logf(v[i] + EPS);
    }
    #pragma unroll
    for (int o = 16; o > 0; o >>= 1) ej += __shfl_xor_sync(0xffffffffu, ej, o);

    float es = cs * logf(cs + EPS);
    #pragma unroll
    for (int o = 16; o > 0; o >>= 1) es += __shfl_xor_sync(0xffffffffu, es, o);

    #pragma unroll
    for (int o = 16; o > 0; o >>= 1) {
        #pragma unroll
        for (int i = 0; i < 32; i++) v[i] += __shfl_xor_sync(0xffffffffu, v[i], o);
    }
    float et = 0.0f;
    #pragma unroll
    for (int i = 0; i < 32; i++) et += v[i] * logf(v[i] + EPS);

    float val = (et + es) / ej;
    if (lane == 0) part[w] = val;
    __syncthreads();
    if (threadIdx.x == 0)
        out[0] = -(part[0] + part[1] + part[2] + part[3]) * 0.25f;
}

// ---------------------------------------------------------------------------
extern "C" void kernel_launch(void* const* d_in, const int* in_sizes, int n_in,
                              void* d_out, int out_size) {
    const float* tar = (const float*)d_in[0];
    const float* src = (const float*)d_in[1];
    float* out = (float*)d_out;

    static bool attr_set = false;
    if (!attr_set) {
        cudaFuncSetAttribute(k_hist, cudaFuncAttributeMaxDynamicSharedMemorySize,
                             NBINS2 * 32 * sizeof(float));
        attr_set = true;
    }

    k_pre<<<dim3(MM_CTAS, NSAMP), 256>>>(tar, src);
    k_hist<<<dim3(37, NSAMP), 1024, NBINS2 * 32 * sizeof(float)>>>(tar, src);
    k_norm<<<NSAMP, 1024>>>();
    k_final<<<1, 128>>>(out);
}

// round 4
// speedup vs baseline: 14.4478x; 1.4765x over previous
#include <cuda_runtime.h>

// ---------------------------------------------------------------------------
// Problem constants
#define P_ELEMS (96*96*96)          // 884736 points per sample
#define NSAMP   4
#define NB      32
#define NBINS2  (NB*NB)
#define MM_CTAS 37                  // minmax partial CTAs per sample (37*4=148)

// exp(-(d^2)/(2 sigma^2)) with d in bin units: C = 2048/961 = 2.1311134235
// exp2 form: C*log2(e)
#define EXP2_C   3.0745468f
// chain constants
#define G_QTR    0.58697259f        // exp(-0.25*C)
#define G_225    8.2709087e-3f      // exp(-2.25*C)
#define EPS      1e-10f

// ---------------------------------------------------------------------------
// Device scratch (no allocations allowed)
__device__ float g_pmnT[NSAMP*MM_CTAS];
__device__ float g_pmxT[NSAMP*MM_CTAS];
__device__ float g_pmnS[NSAMP*MM_CTAS];
__device__ float g_pmxS[NSAMP*MM_CTAS];
__device__ float g_hist[NSAMP*NBINS2];

// ---------------------------------------------------------------------------
// Pass 1: per-CTA min/max partials (plain stores). Also zeroes g_hist.
__global__ void __launch_bounds__(512) k_pre(const float* __restrict__ tar,
                                             const float* __restrict__ src) {
    int b = blockIdx.y;
    if (b == 0) {
        int idx = blockIdx.x * 512 + threadIdx.x;
        if (idx < NSAMP * NBINS2) g_hist[idx] = 0.0f;
    }

    const float4* t4 = (const float4*)(tar + (size_t)b * P_ELEMS);
    const float4* s4 = (const float4*)(src + (size_t)b * P_ELEMS);
    const int n4 = P_ELEMS / 4;

    float mnT = 1e30f, mxT = -1e30f, mnS = 1e30f, mxS = -1e30f;
    for (int i = blockIdx.x * 512 + threadIdx.x; i < n4; i += MM_CTAS * 512) {
        float4 v = t4[i];
        mnT = fminf(mnT, fminf(fminf(v.x, v.y), fminf(v.z, v.w)));
        mxT = fmaxf(mxT, fmaxf(fmaxf(v.x, v.y), fmaxf(v.z, v.w)));
        float4 u = s4[i];
        mnS = fminf(mnS, fminf(fminf(u.x, u.y), fminf(u.z, u.w)));
        mxS = fmaxf(mxS, fmaxf(fmaxf(u.x, u.y), fmaxf(u.z, u.w)));
    }
    #pragma unroll
    for (int o = 16; o > 0; o >>= 1) {
        mnT = fminf(mnT, __shfl_xor_sync(0xffffffffu, mnT, o));
        mxT = fmaxf(mxT, __shfl_xor_sync(0xffffffffu, mxT, o));
        mnS = fminf(mnS, __shfl_xor_sync(0xffffffffu, mnS, o));
        mxS = fmaxf(mxS, __shfl_xor_sync(0xffffffffu, mxS, o));
    }
    __shared__ float sm[4][16];
    int w = threadIdx.x >> 5;
    if ((threadIdx.x & 31) == 0) {
        sm[0][w] = mnT; sm[1][w] = mxT; sm[2][w] = mnS; sm[3][w] = mxS;
    }
    __syncthreads();
    if (threadIdx.x == 0) {
        float a = sm[0][0], c = sm[1][0], e = sm[2][0], f = sm[3][0];
        #pragma unroll
        for (int i = 1; i < 16; i++) {
            a = fminf(a, sm[0][i]); c = fmaxf(c, sm[1][i]);
            e = fminf(e, sm[2][i]); f = fmaxf(f, sm[3][i]);
        }
        int slot = b * MM_CTAS + blockIdx.x;
        g_pmnT[slot] = a; g_pmxT[slot] = c;
        g_pmnS[slot] = e; g_pmxS[slot] = f;
    }
}

// ---------------------------------------------------------------------------
// 4-wide Gaussian window via ratio chain: 3 EX2 per axis.
// bins i0..i0+3; m = f - (i0+1.5) in [-1.5, 1.5] (|m|<=0.5 unclamped).
// w[k] = exp(-C*(m - (k-1.5))^2)
__device__ __forceinline__ void gauss4(float f, int& i0, float w[4]) {
    i0 = min(max(__float2int_rd(f) - 1, 0), NB - 4);
    float m  = f - (float)i0 - 1.5f;
    float E  = exp2f(-EXP2_C * m * m);
    float R  = exp2f(-EXP2_C * m);        // exp(-C m)
    float Ri = exp2f( EXP2_C * m);        // exp(+C m)
    float a = E * G_QTR;
    w[1] = a * R;                          // d = m+0.5
    w[2] = a * Ri;                         // d = m-0.5
    float b = E * G_225;
    w[0] = b * (R * R * R);                // d = m+1.5
    w[3] = b * (Ri * Ri * Ri);             // d = m-1.5
}

// ---------------------------------------------------------------------------
// Pass 2: joint histogram, 4x4 truncated Gaussian window.
// Lane-interleaved private histograms (bank == lane -> conflict-free ATOMS).
// 128 KB dynamic smem, 1024 threads, 1 CTA/SM, grid = (37, 4) = 1 full wave.
__global__ void __launch_bounds__(1024, 1) k_hist(const float* __restrict__ tar,
                                                  const float* __restrict__ src) {
    extern __shared__ float sh[];           // [NBINS2][32]
    const int b = blockIdx.y;

    float4* z4 = (float4*)sh;
    #pragma unroll
    for (int i = threadIdx.x; i < NBINS2 * 32 / 4; i += 1024)
        z4[i] = make_float4(0.f, 0.f, 0.f, 0.f);

    __shared__ float lim[4];
    if (threadIdx.x < 4) {
        const float* arr = (threadIdx.x == 0) ? g_pmnT :
                           (threadIdx.x == 1) ? g_pmxT :
                           (threadIdx.x == 2) ? g_pmnS : g_pmxS;
        bool ismin = (threadIdx.x & 1) == 0;
        float r = arr[b * MM_CTAS];
        #pragma unroll
        for (int i = 1; i < MM_CTAS; i++) {
            float v = arr[b * MM_CTAS + i];
            r = ismin ? fminf(r, v) : fmaxf(r, v);
        }
        lim[threadIdx.x] = r;
    }
    __syncthreads();

    const float mnT = lim[0], mxT = lim[1], mnS = lim[2], mxS = lim[3];
    const float scT = 31.0f / (mxT - mnT + 1e-12f);
    const float scS = 31.0f / (mxS - mnS + 1e-12f);

    const float4* t4 = (const float4*)(tar + (size_t)b * P_ELEMS);
    const float4* s4 = (const float4*)(src + (size_t)b * P_ELEMS);
    float* hb = sh + (threadIdx.x & 31);    // this lane's copy base
    const int n4 = P_ELEMS / 4;

    for (int p = blockIdx.x * 1024 + threadIdx.x; p < n4; p += 37 * 1024) {
        float4 tv = t4[p];
        float4 sv = s4[p];
        float tf[4] = {tv.x, tv.y, tv.z, tv.w};
        float sf[4] = {sv.x, sv.y, sv.z, sv.w};
        #pragma unroll
        for (int q = 0; q < 4; q++) {
            float ft = (tf[q] - mnT) * scT;     // in [0, 31]
            float fs = (sf[q] - mnS) * scS;
            int it0, js0;
            float wt[4], ws[4];
            gauss4(ft, it0, wt);
            gauss4(fs, js0, ws);

            float* base = hb + ((it0 * NB + js0) << 5);
            #pragma unroll
            for (int k = 0; k < 4; k++) {
                float w = wt[k];
                #pragma unroll
                for (int l = 0; l < 4; l++) {
                    atomicAdd(base + (((k * NB) + l) << 5), w * ws[l]);
                }
            }
        }
    }

    __syncthreads();
    // merge 32 lane copies per bin, rotated reads (conflict-free)
    const int lane = threadIdx.x & 31;
    for (int bin = threadIdx.x; bin < NBINS2; bin += 1024) {
        const float* c = sh + (bin << 5);
        float s = 0.0f;
        #pragma unroll
        for (int i = 0; i < 32; i++) s += c[(lane + i) & 31];
        atomicAdd(&g_hist[b * NBINS2 + bin], s);
    }
}

// ---------------------------------------------------------------------------
// Pass 3: norm + entropies + loss. 1 CTA, warp w = sample w.
__global__ void __launch_bounds__(128) k_final(float* __restrict__ out) {
    __shared__ float smp[4][32][33];   // p, transposed access for row sums
    __shared__ float part[4];
    const int w = threadIdx.x >> 5, lane = threadIdx.x & 31;

    float v[32];
    #pragma unroll
    for (int i = 0; i < 32; i++)
        v[i] = g_hist[w * NBINS2 + i * NB + lane];   // column 'lane'

    // norm over all 1024 entries
    float cs = 0.0f;
    #pragma unroll
    for (int i = 0; i < 32; i++) cs += v[i];
    float norm = cs;
    #pragma unroll
    for (int o = 16; o > 0; o >>= 1) norm += __shfl_xor_sync(0xffffffffu, norm, o);
    float inv = __frcp_rn(norm);

    // joint entropy term + store p to smem
    float ej = 0.0f;
    #pragma unroll
    for (int i = 0; i < 32; i++) {
        float p = v[i] * inv;
        smp[w][i][lane] = p;
        ej += p * __logf(p + EPS);
    }
    #pragma unroll
    for (int o = 16; o > 0; o >>= 1) ej += __shfl_xor_sync(0xffffffffu, ej, o);

    // src (column) marginal entropy term
    float q = cs * inv;
    float es = q * __logf(q + EPS);
    #pragma unroll
    for (int o = 16; o > 0; o >>= 1) es += __shfl_xor_sync(0xffffffffu, es, o);

    __syncwarp();
    // tar (row) marginal: lane sums row 'lane' from smem (conflict-free, 33-stride)
    float r = 0.0f;
    #pragma unroll
    for (int j = 0; j < 32; j++) r += smp[w][lane][j];
    float et = r * __logf(r + EPS);
    #pragma unroll
    for (int o = 16; o > 0; o >>= 1) et += __shfl_xor_sync(0xffffffffu, et, o);

    if (lane == 0) part[w] = (et + es) / ej;
    __syncthreads();
    if (threadIdx.x == 0)
        out[0] = -(part[0] + part[1] + part[2] + part[3]) * 0.25f;
}

// ---------------------------------------------------------------------------
extern "C" void kernel_launch(void* const* d_in, const int* in_sizes, int n_in,
                              void* d_out, int out_size) {
    const float* tar = (const float*)d_in[0];
    const float* src = (const float*)d_in[1];
    float* out = (float*)d_out;

    static bool attr_set = false;
    if (!attr_set) {
        cudaFuncSetAttribute(k_hist, cudaFuncAttributeMaxDynamicSharedMemorySize,
                             NBINS2 * 32 * sizeof(float));
        attr_set = true;
    }

    k_pre<<<dim3(MM_CTAS, NSAMP), 512>>>(tar, src);
    k_hist<<<dim3(37, NSAMP), 1024, NBINS2 * 32 * sizeof(float)>>>(tar, src);
    k_final<<<1, 128>>>(out);
}